// round 5
// baseline (speedup 1.0000x reference)
#include <cuda_runtime.h>

#define N_NODES   100000
#define N_EDGES   1600000
#define HIDDEN    64
#define EMB       2
#define N_GRAPHS  64

// ---------------- scratch (device globals; no allocation allowed) ----------------
__device__ float  d_dinv[N_NODES];          // degree during pass 1, then rsqrt(deg)
__device__ float  d_xd[N_NODES];            // dinv[n] * x[n]
__device__ float  d_p[N_NODES];             // layer-1 unnormalized sum, then final p
__device__ float2 d_gd[N_NODES];            // dinv[n] * g[n]
__device__ float2 d_u[N_NODES];             // layer-2 unnormalized aggregate
__device__ float  d_sums[2];                // sum(p), sum(p^2)
__device__ float  d_acc[N_GRAPHS * EMB];    // pooled sums
__device__ float  d_cnt[N_GRAPHS];          // nodes per graph
__device__ unsigned d_ticket;               // last-block ticket for k_pool finalize

// Vector reduction: one RED.E.ADD.F32x2 per edge (PTX ISA 8.1+, sm_90+)
__device__ __forceinline__ void red_add_f32x2(float2* addr, float a, float b) {
    asm volatile("red.global.add.v2.f32 [%0], {%1, %2};"
                 :: "l"(addr), "f"(a), "f"(b) : "memory");
}

// ---------------- kernels ----------------

// Init: deg starts at 1.0 (self-loop weight), accumulators at 0.
// (Device globals persist across graph replays — reset is mandatory.)
__global__ void k_init() {
    int i = blockIdx.x * blockDim.x + threadIdx.x;
    if (i < N_NODES) d_dinv[i] = 1.0f;
    if (i < 2) d_sums[i] = 0.0f;
    if (i < N_GRAPHS * EMB) d_acc[i] = 0.0f;
    if (i < N_GRAPHS) d_cnt[i] = 0.0f;
    if (i == 0) d_ticket = 0u;
}

// Pass 1: weighted in-degree  deg[d] += w[e].  8 edges/thread, streamed loads.
__global__ void __launch_bounds__(256)
k_deg(const int* __restrict__ dst, const float* __restrict__ w) {
    int t = blockIdx.x * blockDim.x + threadIdx.x;
    int e = t * 8;
    if (e + 7 < N_EDGES) {
        int4   dA = __ldcs((const int4*)  (dst + e));
        int4   dB = __ldcs((const int4*)  (dst + e + 4));
        float4 wA = __ldcs((const float4*)(w   + e));
        float4 wB = __ldcs((const float4*)(w   + e + 4));
        atomicAdd(&d_dinv[dA.x], wA.x);
        atomicAdd(&d_dinv[dA.y], wA.y);
        atomicAdd(&d_dinv[dA.z], wA.z);
        atomicAdd(&d_dinv[dA.w], wA.w);
        atomicAdd(&d_dinv[dB.x], wB.x);
        atomicAdd(&d_dinv[dB.y], wB.y);
        atomicAdd(&d_dinv[dB.z], wB.z);
        atomicAdd(&d_dinv[dB.w], wB.w);
    } else {
        for (; e < N_EDGES; e++) atomicAdd(&d_dinv[dst[e]], w[e]);
    }
}

// dinv = rsqrt(deg); xd = dinv*x; seed layer-1 sum with self-loop term (=xd).
// (p[d] = dinv[d] * [ Σ_s w*xd[s] + xd[d] ] — dinv[d] applied later in k_stats)
__global__ void k_dinv(const float* __restrict__ x) {
    int n = blockIdx.x * blockDim.x + threadIdx.x;
    if (n >= N_NODES) return;
    float di = rsqrtf(d_dinv[n]);   // deg >= 1 always (self-loop weight 1)
    float xd = di * x[n];
    d_dinv[n] = di;
    d_xd[n] = xd;
    d_p[n] = xd;                    // self-loop seed (unnormalized)
}

// Pass 2: p'[d] += w * xd[s].  Single 4B gather per edge; 8 edges/thread.
__global__ void __launch_bounds__(256)
k_p_edges(const int* __restrict__ src, const int* __restrict__ dst,
          const float* __restrict__ w) {
    int t = blockIdx.x * blockDim.x + threadIdx.x;
    int e = t * 8;
    if (e + 7 < N_EDGES) {
        int4   sA = __ldcs((const int4*)  (src + e));
        int4   sB = __ldcs((const int4*)  (src + e + 4));
        int4   dA = __ldcs((const int4*)  (dst + e));
        int4   dB = __ldcs((const int4*)  (dst + e + 4));
        float4 wA = __ldcs((const float4*)(w   + e));
        float4 wB = __ldcs((const float4*)(w   + e + 4));
        // front-batch all 8 gathers (independent — MLP=8)
        float x0 = __ldg(d_xd + sA.x), x1 = __ldg(d_xd + sA.y);
        float x2 = __ldg(d_xd + sA.z), x3 = __ldg(d_xd + sA.w);
        float x4 = __ldg(d_xd + sB.x), x5 = __ldg(d_xd + sB.y);
        float x6 = __ldg(d_xd + sB.z), x7 = __ldg(d_xd + sB.w);
        atomicAdd(&d_p[dA.x], wA.x * x0);
        atomicAdd(&d_p[dA.y], wA.y * x1);
        atomicAdd(&d_p[dA.z], wA.z * x2);
        atomicAdd(&d_p[dA.w], wA.w * x3);
        atomicAdd(&d_p[dB.x], wB.x * x4);
        atomicAdd(&d_p[dB.y], wB.y * x5);
        atomicAdd(&d_p[dB.z], wB.z * x6);
        atomicAdd(&d_p[dB.w], wB.w * x7);
    } else {
        for (; e < N_EDGES; e++)
            atomicAdd(&d_p[dst[e]], w[e] * __ldg(d_xd + src[e]));
    }
}

// Finalize p = dinv * p'; accumulate sum(p), sum(p^2).
__global__ void k_stats() {
    int tid = threadIdx.x;
    int n = blockIdx.x * blockDim.x + tid;
    float v = 0.0f;
    if (n < N_NODES) {
        v = d_dinv[n] * d_p[n];
        d_p[n] = v;
    }
    float v2 = v * v;
    #pragma unroll
    for (int off = 16; off > 0; off >>= 1) {
        v  += __shfl_down_sync(0xffffffffu, v,  off);
        v2 += __shfl_down_sync(0xffffffffu, v2, off);
    }
    __shared__ float s1[8], s2[8];
    int lane = tid & 31, warp = tid >> 5;
    if (lane == 0) { s1[warp] = v; s2[warp] = v2; }
    __syncthreads();
    if (warp == 0) {
        v  = (lane < 8) ? s1[lane] : 0.0f;
        v2 = (lane < 8) ? s2[lane] : 0.0f;
        #pragma unroll
        for (int off = 4; off > 0; off >>= 1) {
            v  += __shfl_down_sync(0xffffffffu, v,  off);
            v2 += __shfl_down_sync(0xffffffffu, v2, off);
        }
        if (lane == 0) { atomicAdd(&d_sums[0], v); atomicAdd(&d_sums[1], v2); }
    }
}

// Per-node: computes BN coefficients in-block (b1 cancels exactly), then
// g[n] = relu(a*q + beta) @ W2 ; store gd = dinv*g; seed u with gd.
// (t[d] = dinv[d] * [ Σ_s w*gd[s] + gd[d] ] — dinv[d] applied later in k_pool)
__global__ void k_gnode(const float* __restrict__ W1, const float* __restrict__ gamma,
                        const float* __restrict__ beta, const float* __restrict__ W2) {
    __shared__ float sa[HIDDEN], sb[HIDDEN], sw[HIDDEN * EMB];
    int tid = threadIdx.x;
    float mp = d_sums[0] * (1.0f / N_NODES);
    if (tid < HIDDEN) {
        float varp = d_sums[1] * (1.0f / N_NODES) - mp * mp;
        float wj = W1[tid];
        sa[tid] = wj * gamma[tid] * rsqrtf(wj * wj * varp + 1e-5f);
        sb[tid] = beta[tid];
    }
    if (tid < HIDDEN * EMB) sw[tid] = W2[tid];
    __syncthreads();
    int n = blockIdx.x * blockDim.x + tid;
    if (n >= N_NODES) return;
    float q = d_p[n] - mp;
    float g0 = 0.0f, g1 = 0.0f;
    #pragma unroll
    for (int j = 0; j < HIDDEN; j++) {
        float r = fmaxf(sa[j] * q + sb[j], 0.0f);
        g0 = fmaf(r, sw[j * EMB + 0], g0);
        g1 = fmaf(r, sw[j * EMB + 1], g1);
    }
    float di = d_dinv[n];
    float2 gd = make_float2(di * g0, di * g1);
    d_gd[n] = gd;
    d_u[n] = gd;                    // self-loop seed (unnormalized)
}

// Pass 3: u[d] += w * gd[s].  One 8B gather + one f32x2 RED per edge; 8/thread.
__global__ void __launch_bounds__(256)
k_l2_edges(const int* __restrict__ src, const int* __restrict__ dst,
           const float* __restrict__ w) {
    int t = blockIdx.x * blockDim.x + threadIdx.x;
    int e = t * 8;
    if (e + 7 < N_EDGES) {
        int4   sA = __ldcs((const int4*)  (src + e));
        int4   sB = __ldcs((const int4*)  (src + e + 4));
        int4   dA = __ldcs((const int4*)  (dst + e));
        int4   dB = __ldcs((const int4*)  (dst + e + 4));
        float4 wA = __ldcs((const float4*)(w   + e));
        float4 wB = __ldcs((const float4*)(w   + e + 4));
        float2 g0 = d_gd[sA.x], g1 = d_gd[sA.y], g2 = d_gd[sA.z], g3 = d_gd[sA.w];
        float2 g4 = d_gd[sB.x], g5 = d_gd[sB.y], g6 = d_gd[sB.z], g7 = d_gd[sB.w];
        red_add_f32x2(&d_u[dA.x], wA.x * g0.x, wA.x * g0.y);
        red_add_f32x2(&d_u[dA.y], wA.y * g1.x, wA.y * g1.y);
        red_add_f32x2(&d_u[dA.z], wA.z * g2.x, wA.z * g2.y);
        red_add_f32x2(&d_u[dA.w], wA.w * g3.x, wA.w * g3.y);
        red_add_f32x2(&d_u[dB.x], wB.x * g4.x, wB.x * g4.y);
        red_add_f32x2(&d_u[dB.y], wB.y * g5.x, wB.y * g5.y);
        red_add_f32x2(&d_u[dB.z], wB.z * g6.x, wB.z * g6.y);
        red_add_f32x2(&d_u[dB.w], wB.w * g7.x, wB.w * g7.y);
    } else {
        for (; e < N_EDGES; e++) {
            int s = src[e], d = dst[e];
            float2 gs = d_gd[s];
            red_add_f32x2(&d_u[d], w[e] * gs.x, w[e] * gs.y);
        }
    }
}

// Pool: t = dinv*u; shared-memory pre-aggregation, few global atomics, then the
// LAST block (ticket) finalizes out[g,k] = acc/cnt + b2[k]. Deterministic.
__global__ void k_pool(const int* __restrict__ batch, const float* __restrict__ b2,
                       float* __restrict__ out) {
    __shared__ float sacc[N_GRAPHS * EMB];
    __shared__ float scnt[N_GRAPHS];
    __shared__ bool  is_last;
    int tid = threadIdx.x;
    if (tid < N_GRAPHS * EMB) sacc[tid] = 0.0f;
    if (tid < N_GRAPHS) scnt[tid] = 0.0f;
    __syncthreads();
    int n = blockIdx.x * blockDim.x + tid;
    if (n < N_NODES) {
        int b = batch[n];
        float di = d_dinv[n];
        float2 u = d_u[n];
        atomicAdd(&sacc[b * EMB + 0], di * u.x);
        atomicAdd(&sacc[b * EMB + 1], di * u.y);
        atomicAdd(&scnt[b], 1.0f);
    }
    __syncthreads();
    if (tid < N_GRAPHS * EMB) atomicAdd(&d_acc[tid], sacc[tid]);
    if (tid < N_GRAPHS) atomicAdd(&d_cnt[tid], scnt[tid]);
    // last-block finalize
    __threadfence();
    if (tid == 0) {
        unsigned old = atomicInc(&d_ticket, 0xffffffffu);
        is_last = (old == gridDim.x - 1);
    }
    __syncthreads();
    if (is_last && tid < N_GRAPHS * EMB) {
        int g = tid / EMB, k = tid % EMB;
        float acc = *((volatile float*)&d_acc[tid]);   // bypass L1; L2 has atomics
        float cnt = *((volatile float*)&d_cnt[g]);
        out[tid] = acc / fmaxf(cnt, 1.0f) + b2[k];
    }
}

// ---------------- launch ----------------
extern "C" void kernel_launch(void* const* d_in, const int* in_sizes, int n_in,
                              void* d_out, int out_size) {
    const float* x     = (const float*)d_in[0];
    const int*   ei    = (const int*)  d_in[1];   // [2, E]: src row then dst row
    const float* ew    = (const float*)d_in[2];
    const int*   batch = (const int*)  d_in[3];
    const float* W1    = (const float*)d_in[4];
    // d_in[5] = b1 (cancels exactly inside batch-norm; unused)
    const float* gamma = (const float*)d_in[6];
    const float* beta  = (const float*)d_in[7];
    const float* W2    = (const float*)d_in[8];
    const float* b2    = (const float*)d_in[9];
    float* out = (float*)d_out;

    const int* src = ei;
    const int* dst = ei + N_EDGES;

    const int TB = 256;
    const int nodeBlocks  = (N_NODES + TB - 1) / TB;
    const int edgeBlocks8 = (N_EDGES / 8 + TB - 1) / TB;   // 8 edges per thread

    k_init    <<<nodeBlocks, TB>>>();
    k_deg     <<<edgeBlocks8, TB>>>(dst, ew);
    k_dinv    <<<nodeBlocks, TB>>>(x);
    k_p_edges <<<edgeBlocks8, TB>>>(src, dst, ew);
    k_stats   <<<nodeBlocks, TB>>>();
    k_gnode   <<<nodeBlocks, TB>>>(W1, gamma, beta, W2);
    k_l2_edges<<<edgeBlocks8, TB>>>(src, dst, ew);
    k_pool    <<<nodeBlocks, TB>>>(batch, b2, out);
}

// round 6
// speedup vs baseline: 1.0546x; 1.0546x over previous
#include <cuda_runtime.h>

#define N_NODES   100000
#define N_EDGES   1600000
#define HIDDEN    64
#define EMB       2
#define N_GRAPHS  64

#define EDGE_GRID 1184   // 148 SMs x 8 CTAs of 256 threads = exactly 1 wave
#define TB        256
#define N_CHUNK4  (N_EDGES / 4)   // 400000 4-edge chunks (E % 4 == 0)

// ---------------- scratch (device globals; no allocation allowed) ----------------
__device__ float  d_dinv[N_NODES];          // degree during pass 1, then rsqrt(deg)
__device__ float  d_xd[N_NODES];            // dinv[n] * x[n]
__device__ float  d_p[N_NODES];             // layer-1 unnormalized sum, then final p
__device__ float2 d_gd[N_NODES];            // dinv[n] * g[n]
__device__ float2 d_u[N_NODES];             // layer-2 unnormalized aggregate
__device__ float  d_sums[2];                // sum(p), sum(p^2)
__device__ float  d_acc[N_GRAPHS * EMB];    // pooled sums
__device__ float  d_cnt[N_GRAPHS];          // nodes per graph
__device__ unsigned d_ticket;               // last-block ticket for k_pool finalize

// Vector reduction: one RED.E.ADD.F32x2 per edge (PTX ISA 8.1+, sm_90+)
__device__ __forceinline__ void red_add_f32x2(float2* addr, float a, float b) {
    asm volatile("red.global.add.v2.f32 [%0], {%1, %2};"
                 :: "l"(addr), "f"(a), "f"(b) : "memory");
}

// ---------------- kernels ----------------

// Init: deg starts at 1.0 (self-loop weight), accumulators at 0.
// (Device globals persist across graph replays — reset is mandatory.)
__global__ void k_init() {
    int i = blockIdx.x * blockDim.x + threadIdx.x;
    if (i < N_NODES) d_dinv[i] = 1.0f;
    if (i < 2) d_sums[i] = 0.0f;
    if (i < N_GRAPHS * EMB) d_acc[i] = 0.0f;
    if (i < N_GRAPHS) d_cnt[i] = 0.0f;
    if (i == 0) d_ticket = 0u;
}

// Pass 1: weighted in-degree  deg[d] += w[e].  Grid-stride over 4-edge chunks.
__global__ void __launch_bounds__(TB)
k_deg(const int* __restrict__ dst, const float* __restrict__ w) {
    const int stride = EDGE_GRID * TB;
    for (int c = blockIdx.x * TB + threadIdx.x; c < N_CHUNK4; c += stride) {
        int e = c * 4;
        int4   d4 = __ldcs((const int4*)  (dst + e));
        float4 w4 = __ldcs((const float4*)(w   + e));
        atomicAdd(&d_dinv[d4.x], w4.x);
        atomicAdd(&d_dinv[d4.y], w4.y);
        atomicAdd(&d_dinv[d4.z], w4.z);
        atomicAdd(&d_dinv[d4.w], w4.w);
    }
}

// dinv = rsqrt(deg); xd = dinv*x; seed layer-1 sum with self-loop term (=xd).
// (p[d] = dinv[d] * [ Σ_s w*xd[s] + xd[d] ] — dinv[d] applied later in k_stats)
__global__ void k_dinv(const float* __restrict__ x) {
    int n = blockIdx.x * blockDim.x + threadIdx.x;
    if (n >= N_NODES) return;
    float di = rsqrtf(d_dinv[n]);   // deg >= 1 always (self-loop weight 1)
    float xd = di * x[n];
    d_dinv[n] = di;
    d_xd[n] = xd;
    d_p[n] = xd;                    // self-loop seed (unnormalized)
}

// Pass 2: p'[d] += w * xd[s].  Single 4B gather per edge; grid-stride chunks.
__global__ void __launch_bounds__(TB)
k_p_edges(const int* __restrict__ src, const int* __restrict__ dst,
          const float* __restrict__ w) {
    const int stride = EDGE_GRID * TB;
    for (int c = blockIdx.x * TB + threadIdx.x; c < N_CHUNK4; c += stride) {
        int e = c * 4;
        int4   s4 = __ldcs((const int4*)  (src + e));
        int4   d4 = __ldcs((const int4*)  (dst + e));
        float4 w4 = __ldcs((const float4*)(w   + e));
        // front-batch gathers (independent — MLP=4)
        float x0 = __ldg(d_xd + s4.x), x1 = __ldg(d_xd + s4.y);
        float x2 = __ldg(d_xd + s4.z), x3 = __ldg(d_xd + s4.w);
        atomicAdd(&d_p[d4.x], w4.x * x0);
        atomicAdd(&d_p[d4.y], w4.y * x1);
        atomicAdd(&d_p[d4.z], w4.z * x2);
        atomicAdd(&d_p[d4.w], w4.w * x3);
    }
}

// Finalize p = dinv * p'; accumulate sum(p), sum(p^2).
__global__ void k_stats() {
    int tid = threadIdx.x;
    int n = blockIdx.x * blockDim.x + tid;
    float v = 0.0f;
    if (n < N_NODES) {
        v = d_dinv[n] * d_p[n];
        d_p[n] = v;
    }
    float v2 = v * v;
    #pragma unroll
    for (int off = 16; off > 0; off >>= 1) {
        v  += __shfl_down_sync(0xffffffffu, v,  off);
        v2 += __shfl_down_sync(0xffffffffu, v2, off);
    }
    __shared__ float s1[8], s2[8];
    int lane = tid & 31, warp = tid >> 5;
    if (lane == 0) { s1[warp] = v; s2[warp] = v2; }
    __syncthreads();
    if (warp == 0) {
        v  = (lane < 8) ? s1[lane] : 0.0f;
        v2 = (lane < 8) ? s2[lane] : 0.0f;
        #pragma unroll
        for (int off = 4; off > 0; off >>= 1) {
            v  += __shfl_down_sync(0xffffffffu, v,  off);
            v2 += __shfl_down_sync(0xffffffffu, v2, off);
        }
        if (lane == 0) { atomicAdd(&d_sums[0], v); atomicAdd(&d_sums[1], v2); }
    }
}

// Per-node: computes BN coefficients in-block (b1 cancels exactly), then
// g[n] = relu(a*q + beta) @ W2 ; store gd = dinv*g; seed u with gd.
// (t[d] = dinv[d] * [ Σ_s w*gd[s] + gd[d] ] — dinv[d] applied later in k_pool)
__global__ void k_gnode(const float* __restrict__ W1, const float* __restrict__ gamma,
                        const float* __restrict__ beta, const float* __restrict__ W2) {
    __shared__ float sa[HIDDEN], sb[HIDDEN], sw[HIDDEN * EMB];
    int tid = threadIdx.x;
    float mp = d_sums[0] * (1.0f / N_NODES);
    if (tid < HIDDEN) {
        float varp = d_sums[1] * (1.0f / N_NODES) - mp * mp;
        float wj = W1[tid];
        sa[tid] = wj * gamma[tid] * rsqrtf(wj * wj * varp + 1e-5f);
        sb[tid] = beta[tid];
    }
    if (tid < HIDDEN * EMB) sw[tid] = W2[tid];
    __syncthreads();
    int n = blockIdx.x * blockDim.x + tid;
    if (n >= N_NODES) return;
    float q = d_p[n] - mp;
    float g0 = 0.0f, g1 = 0.0f;
    #pragma unroll
    for (int j = 0; j < HIDDEN; j++) {
        float r = fmaxf(sa[j] * q + sb[j], 0.0f);
        g0 = fmaf(r, sw[j * EMB + 0], g0);
        g1 = fmaf(r, sw[j * EMB + 1], g1);
    }
    float di = d_dinv[n];
    float2 gd = make_float2(di * g0, di * g1);
    d_gd[n] = gd;
    d_u[n] = gd;                    // self-loop seed (unnormalized)
}

// Pass 3: u[d] += w * gd[s].  One 8B gather + one f32x2 RED per edge.
__global__ void __launch_bounds__(TB)
k_l2_edges(const int* __restrict__ src, const int* __restrict__ dst,
           const float* __restrict__ w) {
    const int stride = EDGE_GRID * TB;
    for (int c = blockIdx.x * TB + threadIdx.x; c < N_CHUNK4; c += stride) {
        int e = c * 4;
        int4   s4 = __ldcs((const int4*)  (src + e));
        int4   d4 = __ldcs((const int4*)  (dst + e));
        float4 w4 = __ldcs((const float4*)(w   + e));
        float2 g0 = d_gd[s4.x], g1 = d_gd[s4.y], g2 = d_gd[s4.z], g3 = d_gd[s4.w];
        red_add_f32x2(&d_u[d4.x], w4.x * g0.x, w4.x * g0.y);
        red_add_f32x2(&d_u[d4.y], w4.y * g1.x, w4.y * g1.y);
        red_add_f32x2(&d_u[d4.z], w4.z * g2.x, w4.z * g2.y);
        red_add_f32x2(&d_u[d4.w], w4.w * g3.x, w4.w * g3.y);
    }
}

// Pool: t = dinv*u; shared-memory pre-aggregation, few global atomics, then the
// LAST block (ticket) finalizes out[g,k] = acc/cnt + b2[k]. Deterministic.
__global__ void k_pool(const int* __restrict__ batch, const float* __restrict__ b2,
                       float* __restrict__ out) {
    __shared__ float sacc[N_GRAPHS * EMB];
    __shared__ float scnt[N_GRAPHS];
    __shared__ bool  is_last;
    int tid = threadIdx.x;
    if (tid < N_GRAPHS * EMB) sacc[tid] = 0.0f;
    if (tid < N_GRAPHS) scnt[tid] = 0.0f;
    __syncthreads();
    int n = blockIdx.x * blockDim.x + tid;
    if (n < N_NODES) {
        int b = batch[n];
        float di = d_dinv[n];
        float2 u = d_u[n];
        atomicAdd(&sacc[b * EMB + 0], di * u.x);
        atomicAdd(&sacc[b * EMB + 1], di * u.y);
        atomicAdd(&scnt[b], 1.0f);
    }
    __syncthreads();
    if (tid < N_GRAPHS * EMB) atomicAdd(&d_acc[tid], sacc[tid]);
    if (tid < N_GRAPHS) atomicAdd(&d_cnt[tid], scnt[tid]);
    // last-block finalize
    __threadfence();
    if (tid == 0) {
        unsigned old = atomicInc(&d_ticket, 0xffffffffu);
        is_last = (old == gridDim.x - 1);
    }
    __syncthreads();
    if (is_last && tid < N_GRAPHS * EMB) {
        int g = tid / EMB, k = tid % EMB;
        float acc = *((volatile float*)&d_acc[tid]);   // bypass L1; L2 has atomics
        float cnt = *((volatile float*)&d_cnt[g]);
        out[tid] = acc / fmaxf(cnt, 1.0f) + b2[k];
    }
}

// ---------------- launch ----------------
extern "C" void kernel_launch(void* const* d_in, const int* in_sizes, int n_in,
                              void* d_out, int out_size) {
    const float* x     = (const float*)d_in[0];
    const int*   ei    = (const int*)  d_in[1];   // [2, E]: src row then dst row
    const float* ew    = (const float*)d_in[2];
    const int*   batch = (const int*)  d_in[3];
    const float* W1    = (const float*)d_in[4];
    // d_in[5] = b1 (cancels exactly inside batch-norm; unused)
    const float* gamma = (const float*)d_in[6];
    const float* beta  = (const float*)d_in[7];
    const float* W2    = (const float*)d_in[8];
    const float* b2    = (const float*)d_in[9];
    float* out = (float*)d_out;

    const int* src = ei;
    const int* dst = ei + N_EDGES;

    const int nodeBlocks = (N_NODES + TB - 1) / TB;

    k_init    <<<nodeBlocks, TB>>>();
    k_deg     <<<EDGE_GRID, TB>>>(dst, ew);
    k_dinv    <<<nodeBlocks, TB>>>(x);
    k_p_edges <<<EDGE_GRID, TB>>>(src, dst, ew);
    k_stats   <<<nodeBlocks, TB>>>();
    k_gnode   <<<nodeBlocks, TB>>>(W1, gamma, beta, W2);
    k_l2_edges<<<EDGE_GRID, TB>>>(src, dst, ew);
    k_pool    <<<nodeBlocks, TB>>>(batch, b2, out);
}